// round 3
// baseline (speedup 1.0000x reference)
#include <cuda_runtime.h>
#include <float.h>

// ---------------------------------------------------------------------------
// FeatPropagation via uniform-grid EXACT k=3 NN + inverse-distance interp.
//
// Pipeline (6 kernels, one CUDA graph):
//   1. zero_kernel     : clear per-cell counters
//   2. count_kernel    : histogram points into G^3 cells (per batch)
//   3. scan_kernel     : exclusive prefix sum -> cell start offsets (+cursor)
//   4. scatter_kernel  : counting-sort points; store {x,y,z,s2} + orig index
//   5. knn_grid        : per query, expand Chebyshev rings until the top-3
//                        (by the reference's BIT-EXACT GEMM-form d2) provably
//                        cannot change; (d2, index) lexicographic tie-break
//                        makes the result independent of scatter order.
//   6. interp_kernel   : weighted float4 feature gather (L2-bound, ~24us).
//
// Exactness: unseen points have true d2 >= lb^2; reference d2 rounding error
// is < 3e-5, margin is 2e-4, so stop condition can never drop a true top-3.
// ---------------------------------------------------------------------------

#define G      40
#define G3     (G * G * G)
#define GLO    (-4.0f)
#define HV     0.2f
#define INVH   5.0f
#define MAXB   8
#define MARGIN 2e-4f

__device__ int    g_cnt[MAXB * G3];
__device__ int    g_start[MAXB * (G3 + 1)];
__device__ int    g_cur[MAXB * G3];
__device__ float4 g_pts[1 << 15];     // sorted points {x,y,z,s2}, >= Ntot
__device__ int    g_pid[1 << 15];     // sorted -> original global index

#define CAPQ (1 << 18)                // >= 3 * total queries
__device__ int   g_idx[CAPQ];
__device__ float g_w[CAPQ];

__device__ __forceinline__ int cell1(float v) {
    int c = (int)floorf((v - GLO) * INVH);
    return min(max(c, 0), G - 1);
}

__global__ void zero_kernel(int total) {
    int i = blockIdx.x * blockDim.x + threadIdx.x;
    if (i < total) g_cnt[i] = 0;
}

__global__ void count_kernel(const float* __restrict__ xyz, int N, int Ntot) {
    int i = blockIdx.x * blockDim.x + threadIdx.x;
    if (i >= Ntot) return;
    int b = i / N;
    float x = xyz[3 * i], y = xyz[3 * i + 1], z = xyz[3 * i + 2];
    int c = (cell1(z) * G + cell1(y)) * G + cell1(x);
    atomicAdd(&g_cnt[b * G3 + c], 1);
}

__global__ void __launch_bounds__(1024) scan_kernel() {
    const int b   = blockIdx.x;
    const int tid = threadIdx.x;
    const int CH  = (G3 + 1023) / 1024;
    __shared__ int sm[1024];

    const int lo = tid * CH;
    const int hi = min(lo + CH, G3);
    int sum = 0;
    for (int i = lo; i < hi; i++) sum += g_cnt[b * G3 + i];
    sm[tid] = sum;
    __syncthreads();
    for (int off = 1; off < 1024; off <<= 1) {           // Hillis-Steele
        int v = (tid >= off) ? sm[tid - off] : 0;
        __syncthreads();
        sm[tid] += v;
        __syncthreads();
    }
    int run = sm[tid] - sum;                              // exclusive prefix
    for (int i = lo; i < hi; i++) {
        g_start[b * (G3 + 1) + i] = run;
        g_cur[b * G3 + i]         = run;
        run += g_cnt[b * G3 + i];
    }
    if (tid == 1023) g_start[b * (G3 + 1) + G3] = sm[1023];
}

__global__ void scatter_kernel(const float* __restrict__ xyz, int N, int Ntot) {
    int i = blockIdx.x * blockDim.x + threadIdx.x;
    if (i >= Ntot) return;
    int b = i / N;
    float x = xyz[3 * i], y = xyz[3 * i + 1], z = xyz[3 * i + 2];
    int c = (cell1(z) * G + cell1(y)) * G + cell1(x);
    int pos = atomicAdd(&g_cur[b * G3 + c], 1);
    // s2 in the reference's exact arithmetic
    float s2 = __fadd_rn(__fadd_rn(__fmul_rn(x, x), __fmul_rn(y, y)),
                         __fmul_rn(z, z));
    g_pts[b * N + pos] = make_float4(x, y, z, s2);
    g_pid[b * N + pos] = i;          // global index (batch-consistent ordering)
}

#define KNN_BLOCK 128

__global__ void __launch_bounds__(KNN_BLOCK)
knn_grid(const float* __restrict__ qxyz, int N, int M)
{
    const int b = blockIdx.y;
    const int m = blockIdx.x * KNN_BLOCK + threadIdx.x;
    if (m >= M) return;
    const int q = b * M + m;

    const float qx = qxyz[3 * q], qy = qxyz[3 * q + 1], qz = qxyz[3 * q + 2];
    const float q2 = __fadd_rn(__fadd_rn(__fmul_rn(qx, qx), __fmul_rn(qy, qy)),
                               __fmul_rn(qz, qz));
    const int cx = cell1(qx), cy = cell1(qy), cz = cell1(qz);

    float d0 = 1e30f, d1 = 1e30f, d2v = 1e30f;
    int   i0 = -1,    i1 = -1,    i2 = -1;

    const int bs    = b * (G3 + 1);
    const int pbase = b * N;

    // scan sorted points of contiguous cell range [c0, c1]
    auto process = [&](int c0, int c1) {
        const int s = g_start[bs + c0];
        const int e = g_start[bs + c1 + 1];
        for (int p = s; p < e; p++) {
            const float4 P  = g_pts[pbase + p];
            const int    id = g_pid[pbase + p];
            const float cross = __fmaf_rn(qz, P.z,
                                  __fmaf_rn(qy, P.y, __fmul_rn(qx, P.x)));
            const float h  = __fadd_rn(q2, P.w);
            const float dd = __fmaf_rn(-2.0f, cross, h);
            // lexicographic (d2, index) insert == top_k tie-break, order-free
            if (dd < d2v || (dd == d2v && id < i2)) {
                if (dd < d1 || (dd == d1 && id < i1)) {
                    d2v = d1; i2 = i1;
                    if (dd < d0 || (dd == d0 && id < i0)) {
                        d1 = d0; i1 = i0; d0 = dd; i0 = id;
                    } else { d1 = dd; i1 = id; }
                } else { d2v = dd; i2 = id; }
            }
        }
    };

    for (int r = 0; ; r++) {
        const int zlo = max(cz - r, 0), zhi = min(cz + r, G - 1);
        const int ylo = max(cy - r, 0), yhi = min(cy + r, G - 1);
        const int xlo = max(cx - r, 0), xhi = min(cx + r, G - 1);
        for (int z = zlo; z <= zhi; z++) {
            const bool ez = (z == cz - r) || (z == cz + r);
            for (int y = ylo; y <= yhi; y++) {
                const bool ey = ez || (y == cy - r) || (y == cy + r);
                const int row = (z * G + y) * G;
                if (ey) {
                    process(row + xlo, row + xhi);       // full contiguous row
                } else {                                  // interior row: ends
                    if (cx - r >= 0)     process(row + cx - r, row + cx - r);
                    if (cx + r <= G - 1) process(row + cx + r, row + cx + r);
                }
            }
        }
        // lower bound on distance to any cell outside the Chebyshev-r box;
        // sides where the box reaches the grid edge are covered (clamping
        // folds all outliers into edge cells) -> +inf.
        const float fxl = (cx - r <= 0)     ? 1e30f : qx - (GLO + (cx - r) * HV);
        const float fxh = (cx + r >= G - 1) ? 1e30f : (GLO + (cx + r + 1) * HV) - qx;
        const float fyl = (cy - r <= 0)     ? 1e30f : qy - (GLO + (cy - r) * HV);
        const float fyh = (cy + r >= G - 1) ? 1e30f : (GLO + (cy + r + 1) * HV) - qy;
        const float fzl = (cz - r <= 0)     ? 1e30f : qz - (GLO + (cz - r) * HV);
        const float fzh = (cz + r >= G - 1) ? 1e30f : (GLO + (cz + r + 1) * HV) - qz;
        const float lb  = fminf(fminf(fminf(fxl, fxh), fminf(fyl, fyh)),
                                fminf(fzl, fzh));
        if (lb >= 1e29f) break;                           // whole grid visited
        if (i2 >= 0 && lb > 0.0f && d2v + MARGIN <= lb * lb) break;
    }

    // weights: dist = sqrt(max(d2,1e-12)); w = (1/(dist+eps)) / sum
    const float e0 = sqrtf(fmaxf(d0,  1e-12f));
    const float e1 = sqrtf(fmaxf(d1,  1e-12f));
    const float e2 = sqrtf(fmaxf(d2v, 1e-12f));
    const float r0 = __fdiv_rn(1.0f, __fadd_rn(e0, 1e-8f));
    const float r1 = __fdiv_rn(1.0f, __fadd_rn(e1, 1e-8f));
    const float r2 = __fdiv_rn(1.0f, __fadd_rn(e2, 1e-8f));
    const float s  = __fadd_rn(__fadd_rn(r0, r1), r2);

    const int base  = 3 * q;
    g_idx[base + 0] = i0;
    g_idx[base + 1] = i1;
    g_idx[base + 2] = i2;
    g_w[base + 0]   = __fdiv_rn(r0, s);
    g_w[base + 1]   = __fdiv_rn(r1, s);
    g_w[base + 2]   = __fdiv_rn(r2, s);
}

__global__ void __launch_bounds__(256)
interp_kernel(const float* __restrict__ feat, float* __restrict__ out,
              int C4, int total)
{
    const int t = blockIdx.x * 256 + threadIdx.x;
    if (t >= total) return;

    const int q  = t / C4;
    const int cg = t - q * C4;

    const int   base = 3 * q;
    const int   i0 = g_idx[base + 0];
    const int   i1 = g_idx[base + 1];
    const int   i2 = g_idx[base + 2];
    const float w0 = g_w[base + 0];
    const float w1 = g_w[base + 1];
    const float w2 = g_w[base + 2];

    const float4* f = reinterpret_cast<const float4*>(feat);
    const float4 a = __ldg(f + (size_t)i0 * C4 + cg);
    const float4 b = __ldg(f + (size_t)i1 * C4 + cg);
    const float4 c = __ldg(f + (size_t)i2 * C4 + cg);

    float4 o;
    o.x = fmaf(w2, c.x, fmaf(w1, b.x, w0 * a.x));
    o.y = fmaf(w2, c.y, fmaf(w1, b.y, w0 * a.y));
    o.z = fmaf(w2, c.z, fmaf(w1, b.z, w0 * a.z));
    o.w = fmaf(w2, c.w, fmaf(w1, b.w, w0 * a.w));

    reinterpret_cast<float4*>(out)[t] = o;
}

extern "C" void kernel_launch(void* const* d_in, const int* in_sizes, int n_in,
                              void* d_out, int out_size)
{
    const float* xyz     = (const float*)d_in[0];
    const float* new_xyz = (const float*)d_in[1];
    const float* feat    = (const float*)d_in[2];

    const int B    = in_sizes[3];
    const int Ntot = in_sizes[0] / 3;
    const int Mtot = in_sizes[1] / 3;
    const int N    = Ntot / B;
    const int M    = Mtot / B;
    const int C    = in_sizes[2] / Ntot;

    // grid build
    const int cells = B * G3;
    zero_kernel<<<(cells + 255) / 256, 256>>>(cells);
    count_kernel<<<(Ntot + 255) / 256, 256>>>(xyz, N, Ntot);
    scan_kernel<<<B, 1024>>>();
    scatter_kernel<<<(Ntot + 255) / 256, 256>>>(xyz, N, Ntot);

    // exact kNN via ring expansion
    dim3 g1((M + KNN_BLOCK - 1) / KNN_BLOCK, B);
    knn_grid<<<g1, KNN_BLOCK>>>(new_xyz, N, M);

    // weighted feature gather
    const int C4    = C / 4;
    const int total = Mtot * C4;
    interp_kernel<<<(total + 255) / 256, 256>>>(feat, (float*)d_out, C4, total);
}

// round 5
// speedup vs baseline: 1.0122x; 1.0122x over previous
#include <cuda_runtime.h>
#include <float.h>

// ---------------------------------------------------------------------------
// FeatPropagation via uniform-grid EXACT k=3 NN + inverse-distance interp.
//
// R5 == R4 (sort points AND queries for warp-coherent ring walks) with the
// fatal bug fixed: R4 passed __device__ symbols as kernel args from host
// (host shadow address != device address -> garbage). Now all global-array
// selection happens device-side via a template<bool> parameter.
//
// Ranking is BIT-EXACT vs the JAX reference (GEMM-form d2, explicit-rounding
// intrinsics); (d2, index) lexicographic insert == top_k lowest-index
// tie-break, independent of nondeterministic scatter order. Ring stop bound
// conservative (MARGIN >> reference rounding error) -> exact result.
// ---------------------------------------------------------------------------

#define G      40
#define G3     (G * G * G)
#define GLO    (-4.0f)
#define HV     0.2f
#define INVH   5.0f
#define MAXB   8
#define MARGIN 2e-4f

// point grid
__device__ int    g_cnt[MAXB * G3];
__device__ int    g_start[MAXB * (G3 + 1)];
__device__ int    g_cur[MAXB * G3];
__device__ float4 g_pts[1 << 15];      // sorted points {x,y,z,s2}
__device__ int    g_pid[1 << 15];      // sorted slot -> original global index
// query grid
__device__ int    g_qcnt[MAXB * G3];
__device__ int    g_qstart[MAXB * (G3 + 1)];
__device__ int    g_qcur[MAXB * G3];
__device__ float4 g_qpts[1 << 17];     // sorted queries {x,y,z,q2} (>=65536)
__device__ int    g_qid[1 << 17];      // sorted slot -> original global index

#define CAPQ (3 * (1 << 17))
__device__ int   g_idx[CAPQ];
__device__ float g_w[CAPQ];

__device__ __forceinline__ int cell1(float v) {
    int c = (int)floorf((v - GLO) * INVH);
    return min(max(c, 0), G - 1);
}

__global__ void zero_kernel(int cells) {
    int i = blockIdx.x * blockDim.x + threadIdx.x;
    if (i < cells) { g_cnt[i] = 0; g_qcnt[i] = 0; }
}

// QRY=false: points -> g_cnt ; QRY=true: queries -> g_qcnt
template <bool QRY>
__global__ void count_kernel(const float* __restrict__ src, int P, int total) {
    int i = blockIdx.x * blockDim.x + threadIdx.x;
    if (i >= total) return;
    int b = i / P;
    float x = src[3 * i], y = src[3 * i + 1], z = src[3 * i + 2];
    int c = (cell1(z) * G + cell1(y)) * G + cell1(x);
    atomicAdd((QRY ? g_qcnt : g_cnt) + b * G3 + c, 1);
}

// grid (B, 2): y==0 scans point counters, y==1 scans query counters
__global__ void __launch_bounds__(1024) scan_kernel() {
    const int b = blockIdx.x;
    int* cnt   = (blockIdx.y ? g_qcnt   : g_cnt)   + b * G3;
    int* start = (blockIdx.y ? g_qstart : g_start) + b * (G3 + 1);
    int* cur   = (blockIdx.y ? g_qcur   : g_cur)   + b * G3;

    const int tid = threadIdx.x;
    const int CH  = (G3 + 1023) / 1024;
    __shared__ int sm[1024];

    const int lo = tid * CH;
    const int hi = min(lo + CH, G3);
    int sum = 0;
    for (int i = lo; i < hi; i++) sum += cnt[i];
    sm[tid] = sum;
    __syncthreads();
    for (int off = 1; off < 1024; off <<= 1) {            // Hillis-Steele
        int v = (tid >= off) ? sm[tid - off] : 0;
        __syncthreads();
        sm[tid] += v;
        __syncthreads();
    }
    int run = sm[tid] - sum;                              // exclusive prefix
    for (int i = lo; i < hi; i++) {
        start[i] = run;
        cur[i]   = run;
        run += cnt[i];
    }
    if (tid == 1023) start[G3] = sm[1023];
}

// counting-sort scatter; payload {x,y,z,sumsq} + original index
template <bool QRY>
__global__ void scatter_kernel(const float* __restrict__ src, int P, int total) {
    int i = blockIdx.x * blockDim.x + threadIdx.x;
    if (i >= total) return;
    int b = i / P;
    float x = src[3 * i], y = src[3 * i + 1], z = src[3 * i + 2];
    int c = (cell1(z) * G + cell1(y)) * G + cell1(x);
    int pos = atomicAdd((QRY ? g_qcur : g_cur) + b * G3 + c, 1);
    float s2 = __fadd_rn(__fadd_rn(__fmul_rn(x, x), __fmul_rn(y, y)),
                         __fmul_rn(z, z));
    if (QRY) { g_qpts[b * P + pos] = make_float4(x, y, z, s2);
               g_qid [b * P + pos] = i; }
    else     { g_pts [b * P + pos] = make_float4(x, y, z, s2);
               g_pid [b * P + pos] = i; }
}

#define KNN_BLOCK 128

__global__ void __launch_bounds__(KNN_BLOCK)
knn_grid(int N, int M)
{
    const int b = blockIdx.y;
    const int m = blockIdx.x * KNN_BLOCK + threadIdx.x;
    if (m >= M) return;
    const int j = b * M + m;              // SORTED query slot (warp-coherent)

    const float4 Q  = g_qpts[j];
    const int   qid = g_qid[j];
    const float qx = Q.x, qy = Q.y, qz = Q.z, q2 = Q.w;
    const int cx = cell1(qx), cy = cell1(qy), cz = cell1(qz);

    float d0 = 1e30f, d1 = 1e30f, d2v = 1e30f;
    int   i0 = -1,    i1 = -1,    i2 = -1;

    const int bs    = b * (G3 + 1);
    const int pbase = b * N;

    auto process = [&](int c0, int c1) {
        const int s = __ldg(&g_start[bs + c0]);
        const int e = __ldg(&g_start[bs + c1 + 1]);
        for (int p = s; p < e; p++) {
            const float4 P  = g_pts[pbase + p];
            const int    id = g_pid[pbase + p];
            const float cross = __fmaf_rn(qz, P.z,
                                  __fmaf_rn(qy, P.y, __fmul_rn(qx, P.x)));
            const float h  = __fadd_rn(q2, P.w);
            const float dd = __fmaf_rn(-2.0f, cross, h);
            if (dd < d2v || (dd == d2v && id < i2)) {
                if (dd < d1 || (dd == d1 && id < i1)) {
                    d2v = d1; i2 = i1;
                    if (dd < d0 || (dd == d0 && id < i0)) {
                        d1 = d0; i1 = i0; d0 = dd; i0 = id;
                    } else { d1 = dd; i1 = id; }
                } else { d2v = dd; i2 = id; }
            }
        }
    };

    for (int r = 0; ; r++) {
        const int zlo = max(cz - r, 0), zhi = min(cz + r, G - 1);
        const int ylo = max(cy - r, 0), yhi = min(cy + r, G - 1);
        const int xlo = max(cx - r, 0), xhi = min(cx + r, G - 1);
        for (int z = zlo; z <= zhi; z++) {
            const bool ez = (z == cz - r) || (z == cz + r);
            for (int y = ylo; y <= yhi; y++) {
                const bool ey = ez || (y == cy - r) || (y == cy + r);
                const int row = (z * G + y) * G;
                if (ey) {
                    process(row + xlo, row + xhi);        // full contiguous row
                } else {                                   // interior: ends only
                    if (cx - r >= 0)     process(row + cx - r, row + cx - r);
                    if (cx + r <= G - 1) process(row + cx + r, row + cx + r);
                }
            }
        }
        // lower bound to anything outside the Chebyshev-r box; grid-edge
        // sides are fully covered (clamping folds outliers in) -> +inf.
        const float fxl = (cx - r <= 0)     ? 1e30f : qx - (GLO + (cx - r) * HV);
        const float fxh = (cx + r >= G - 1) ? 1e30f : (GLO + (cx + r + 1) * HV) - qx;
        const float fyl = (cy - r <= 0)     ? 1e30f : qy - (GLO + (cy - r) * HV);
        const float fyh = (cy + r >= G - 1) ? 1e30f : (GLO + (cy + r + 1) * HV) - qy;
        const float fzl = (cz - r <= 0)     ? 1e30f : qz - (GLO + (cz - r) * HV);
        const float fzh = (cz + r >= G - 1) ? 1e30f : (GLO + (cz + r + 1) * HV) - qz;
        const float lb  = fminf(fminf(fminf(fxl, fxh), fminf(fyl, fyh)),
                                fminf(fzl, fzh));
        if (lb >= 1e29f) break;
        if (i2 >= 0 && lb > 0.0f && d2v + MARGIN <= lb * lb) break;
    }

    const float e0 = sqrtf(fmaxf(d0,  1e-12f));
    const float e1 = sqrtf(fmaxf(d1,  1e-12f));
    const float e2 = sqrtf(fmaxf(d2v, 1e-12f));
    const float r0 = __fdiv_rn(1.0f, __fadd_rn(e0, 1e-8f));
    const float r1 = __fdiv_rn(1.0f, __fadd_rn(e1, 1e-8f));
    const float r2 = __fdiv_rn(1.0f, __fadd_rn(e2, 1e-8f));
    const float s  = __fadd_rn(__fadd_rn(r0, r1), r2);

    const int base  = 3 * qid;            // write back via ORIGINAL id
    g_idx[base + 0] = i0;
    g_idx[base + 1] = i1;
    g_idx[base + 2] = i2;
    g_w[base + 0]   = __fdiv_rn(r0, s);
    g_w[base + 1]   = __fdiv_rn(r1, s);
    g_w[base + 2]   = __fdiv_rn(r2, s);
}

__global__ void __launch_bounds__(256)
interp_kernel(const float* __restrict__ feat, float* __restrict__ out,
              int C4, int total)
{
    const int t = blockIdx.x * 256 + threadIdx.x;
    if (t >= total) return;

    const int q  = t / C4;
    const int cg = t - q * C4;

    const int   base = 3 * q;
    const int   i0 = g_idx[base + 0];
    const int   i1 = g_idx[base + 1];
    const int   i2 = g_idx[base + 2];
    const float w0 = g_w[base + 0];
    const float w1 = g_w[base + 1];
    const float w2 = g_w[base + 2];

    const float4* f = reinterpret_cast<const float4*>(feat);
    const float4 a = __ldg(f + (size_t)i0 * C4 + cg);
    const float4 b = __ldg(f + (size_t)i1 * C4 + cg);
    const float4 c = __ldg(f + (size_t)i2 * C4 + cg);

    float4 o;
    o.x = fmaf(w2, c.x, fmaf(w1, b.x, w0 * a.x));
    o.y = fmaf(w2, c.y, fmaf(w1, b.y, w0 * a.y));
    o.z = fmaf(w2, c.z, fmaf(w1, b.z, w0 * a.z));
    o.w = fmaf(w2, c.w, fmaf(w1, b.w, w0 * a.w));

    reinterpret_cast<float4*>(out)[t] = o;
}

extern "C" void kernel_launch(void* const* d_in, const int* in_sizes, int n_in,
                              void* d_out, int out_size)
{
    const float* xyz     = (const float*)d_in[0];
    const float* new_xyz = (const float*)d_in[1];
    const float* feat    = (const float*)d_in[2];

    const int B    = in_sizes[3];
    const int Ntot = in_sizes[0] / 3;
    const int Mtot = in_sizes[1] / 3;
    const int N    = Ntot / B;
    const int M    = Mtot / B;
    const int C    = in_sizes[2] / Ntot;

    const int cells = B * G3;
    zero_kernel<<<(cells + 255) / 256, 256>>>(cells);
    count_kernel<false><<<(Ntot + 255) / 256, 256>>>(xyz, N, Ntot);
    count_kernel<true ><<<(Mtot + 255) / 256, 256>>>(new_xyz, M, Mtot);
    scan_kernel<<<dim3(B, 2), 1024>>>();
    scatter_kernel<false><<<(Ntot + 255) / 256, 256>>>(xyz, N, Ntot);
    scatter_kernel<true ><<<(Mtot + 255) / 256, 256>>>(new_xyz, M, Mtot);

    dim3 g1((M + KNN_BLOCK - 1) / KNN_BLOCK, B);
    knn_grid<<<g1, KNN_BLOCK>>>(N, M);

    const int C4    = C / 4;
    const int total = Mtot * C4;
    interp_kernel<<<(total + 255) / 256, 256>>>(feat, (float*)d_out, C4, total);
}

// round 6
// speedup vs baseline: 2.7406x; 2.7076x over previous
#include <cuda_runtime.h>
#include <float.h>

// ---------------------------------------------------------------------------
// FeatPropagation via uniform-grid EXACT k=3 NN + inverse-distance interp.
//
// R6: G=16 (cell 0.5, ~1 pt/cell avg, ~30 in the Gaussian core) replaces
// R5's G=40 (0.064 pt/cell) which burned 99us in scan and made the ring walk
// touch mostly-empty cells. Points AND queries counting-sorted for
// warp-coherent walks.
//
// Ranking is BIT-EXACT vs the JAX reference (GEMM-form d2, explicit-rounding
// intrinsics); (d2, index) lexicographic insert == top_k lowest-index
// tie-break, independent of nondeterministic scatter order. Ring stop bound
// conservative (MARGIN >> reference rounding error) -> exact result.
// ---------------------------------------------------------------------------

#define G      16
#define G3     (G * G * G)
#define GLO    (-4.0f)
#define HV     0.5f
#define INVH   2.0f
#define MAXB   8
#define MARGIN 2e-4f

// point grid
__device__ int    g_cnt[MAXB * G3];
__device__ int    g_start[MAXB * (G3 + 1)];
__device__ int    g_cur[MAXB * G3];
__device__ float4 g_pts[1 << 15];      // sorted points {x,y,z,s2}
__device__ int    g_pid[1 << 15];      // sorted slot -> original global index
// query grid
__device__ int    g_qcnt[MAXB * G3];
__device__ int    g_qstart[MAXB * (G3 + 1)];
__device__ int    g_qcur[MAXB * G3];
__device__ float4 g_qpts[1 << 17];     // sorted queries {x,y,z,q2}
__device__ int    g_qid[1 << 17];      // sorted slot -> original global index

#define CAPQ (3 * (1 << 17))
__device__ int   g_idx[CAPQ];
__device__ float g_w[CAPQ];

__device__ __forceinline__ int cell1(float v) {
    int c = (int)floorf((v - GLO) * INVH);
    return min(max(c, 0), G - 1);
}

__global__ void zero_kernel(int cells) {
    int i = blockIdx.x * blockDim.x + threadIdx.x;
    if (i < cells) { g_cnt[i] = 0; g_qcnt[i] = 0; }
}

// QRY=false: points -> g_cnt ; QRY=true: queries -> g_qcnt
template <bool QRY>
__global__ void count_kernel(const float* __restrict__ src, int P, int total) {
    int i = blockIdx.x * blockDim.x + threadIdx.x;
    if (i >= total) return;
    int b = i / P;
    float x = src[3 * i], y = src[3 * i + 1], z = src[3 * i + 2];
    int c = (cell1(z) * G + cell1(y)) * G + cell1(x);
    atomicAdd((QRY ? g_qcnt : g_cnt) + b * G3 + c, 1);
}

// grid (B, 2): y==0 scans point counters, y==1 scans query counters.
// G3=4096 cells -> 4 per thread; Hillis-Steele over 1024 threads.
__global__ void __launch_bounds__(1024) scan_kernel() {
    const int b = blockIdx.x;
    int* cnt   = (blockIdx.y ? g_qcnt   : g_cnt)   + b * G3;
    int* start = (blockIdx.y ? g_qstart : g_start) + b * (G3 + 1);
    int* cur   = (blockIdx.y ? g_qcur   : g_cur)   + b * G3;

    const int tid = threadIdx.x;
    const int CH  = G3 / 1024;                            // 4
    __shared__ int sm[1024];

    const int lo = tid * CH;
    int c0 = cnt[lo], c1 = cnt[lo + 1], c2 = cnt[lo + 2], c3 = cnt[lo + 3];
    const int sum = c0 + c1 + c2 + c3;
    sm[tid] = sum;
    __syncthreads();
    for (int off = 1; off < 1024; off <<= 1) {            // Hillis-Steele
        int v = (tid >= off) ? sm[tid - off] : 0;
        __syncthreads();
        sm[tid] += v;
        __syncthreads();
    }
    int run = sm[tid] - sum;                              // exclusive prefix
    start[lo]     = run;       cur[lo]     = run;       run += c0;
    start[lo + 1] = run;       cur[lo + 1] = run;       run += c1;
    start[lo + 2] = run;       cur[lo + 2] = run;       run += c2;
    start[lo + 3] = run;       cur[lo + 3] = run;
    if (tid == 1023) start[G3] = sm[1023];
}

// counting-sort scatter; payload {x,y,z,sumsq} + original index
template <bool QRY>
__global__ void scatter_kernel(const float* __restrict__ src, int P, int total) {
    int i = blockIdx.x * blockDim.x + threadIdx.x;
    if (i >= total) return;
    int b = i / P;
    float x = src[3 * i], y = src[3 * i + 1], z = src[3 * i + 2];
    int c = (cell1(z) * G + cell1(y)) * G + cell1(x);
    int pos = atomicAdd((QRY ? g_qcur : g_cur) + b * G3 + c, 1);
    float s2 = __fadd_rn(__fadd_rn(__fmul_rn(x, x), __fmul_rn(y, y)),
                         __fmul_rn(z, z));
    if (QRY) { g_qpts[b * P + pos] = make_float4(x, y, z, s2);
               g_qid [b * P + pos] = i; }
    else     { g_pts [b * P + pos] = make_float4(x, y, z, s2);
               g_pid [b * P + pos] = i; }
}

#define KNN_BLOCK 128

__global__ void __launch_bounds__(KNN_BLOCK)
knn_grid(int N, int M)
{
    const int b = blockIdx.y;
    const int m = blockIdx.x * KNN_BLOCK + threadIdx.x;
    if (m >= M) return;
    const int j = b * M + m;              // SORTED query slot (warp-coherent)

    const float4 Q  = g_qpts[j];
    const int   qid = g_qid[j];
    const float qx = Q.x, qy = Q.y, qz = Q.z, q2 = Q.w;
    const int cx = cell1(qx), cy = cell1(qy), cz = cell1(qz);

    float d0 = 1e30f, d1 = 1e30f, d2v = 1e30f;
    int   i0 = -1,    i1 = -1,    i2 = -1;

    const int bs    = b * (G3 + 1);
    const int pbase = b * N;

    auto process = [&](int c0, int c1) {
        const int s = __ldg(&g_start[bs + c0]);
        const int e = __ldg(&g_start[bs + c1 + 1]);
        for (int p = s; p < e; p++) {
            const float4 P  = g_pts[pbase + p];
            const int    id = g_pid[pbase + p];
            const float cross = __fmaf_rn(qz, P.z,
                                  __fmaf_rn(qy, P.y, __fmul_rn(qx, P.x)));
            const float h  = __fadd_rn(q2, P.w);
            const float dd = __fmaf_rn(-2.0f, cross, h);
            if (dd < d2v || (dd == d2v && id < i2)) {
                if (dd < d1 || (dd == d1 && id < i1)) {
                    d2v = d1; i2 = i1;
                    if (dd < d0 || (dd == d0 && id < i0)) {
                        d1 = d0; i1 = i0; d0 = dd; i0 = id;
                    } else { d1 = dd; i1 = id; }
                } else { d2v = dd; i2 = id; }
            }
        }
    };

    for (int r = 0; ; r++) {
        const int zlo = max(cz - r, 0), zhi = min(cz + r, G - 1);
        const int ylo = max(cy - r, 0), yhi = min(cy + r, G - 1);
        const int xlo = max(cx - r, 0), xhi = min(cx + r, G - 1);
        for (int z = zlo; z <= zhi; z++) {
            const bool ez = (z == cz - r) || (z == cz + r);
            for (int y = ylo; y <= yhi; y++) {
                const bool ey = ez || (y == cy - r) || (y == cy + r);
                const int row = (z * G + y) * G;
                if (ey) {
                    process(row + xlo, row + xhi);        // full contiguous row
                } else {                                   // interior: ends only
                    if (cx - r >= 0)     process(row + cx - r, row + cx - r);
                    if (cx + r <= G - 1) process(row + cx + r, row + cx + r);
                }
            }
        }
        // lower bound to anything outside the Chebyshev-r box; grid-edge
        // sides are fully covered (clamping folds outliers in) -> +inf.
        const float fxl = (cx - r <= 0)     ? 1e30f : qx - (GLO + (cx - r) * HV);
        const float fxh = (cx + r >= G - 1) ? 1e30f : (GLO + (cx + r + 1) * HV) - qx;
        const float fyl = (cy - r <= 0)     ? 1e30f : qy - (GLO + (cy - r) * HV);
        const float fyh = (cy + r >= G - 1) ? 1e30f : (GLO + (cy + r + 1) * HV) - qy;
        const float fzl = (cz - r <= 0)     ? 1e30f : qz - (GLO + (cz - r) * HV);
        const float fzh = (cz + r >= G - 1) ? 1e30f : (GLO + (cz + r + 1) * HV) - qz;
        const float lb  = fminf(fminf(fminf(fxl, fxh), fminf(fyl, fyh)),
                                fminf(fzl, fzh));
        if (lb >= 1e29f) break;
        if (i2 >= 0 && lb > 0.0f && d2v + MARGIN <= lb * lb) break;
    }

    const float e0 = sqrtf(fmaxf(d0,  1e-12f));
    const float e1 = sqrtf(fmaxf(d1,  1e-12f));
    const float e2 = sqrtf(fmaxf(d2v, 1e-12f));
    const float r0 = __fdiv_rn(1.0f, __fadd_rn(e0, 1e-8f));
    const float r1 = __fdiv_rn(1.0f, __fadd_rn(e1, 1e-8f));
    const float r2 = __fdiv_rn(1.0f, __fadd_rn(e2, 1e-8f));
    const float s  = __fadd_rn(__fadd_rn(r0, r1), r2);

    const int base  = 3 * qid;            // write back via ORIGINAL id
    g_idx[base + 0] = i0;
    g_idx[base + 1] = i1;
    g_idx[base + 2] = i2;
    g_w[base + 0]   = __fdiv_rn(r0, s);
    g_w[base + 1]   = __fdiv_rn(r1, s);
    g_w[base + 2]   = __fdiv_rn(r2, s);
}

__global__ void __launch_bounds__(256)
interp_kernel(const float* __restrict__ feat, float* __restrict__ out,
              int C4, int total)
{
    const int t = blockIdx.x * 256 + threadIdx.x;
    if (t >= total) return;

    const int q  = t / C4;
    const int cg = t - q * C4;

    const int   base = 3 * q;
    const int   i0 = g_idx[base + 0];
    const int   i1 = g_idx[base + 1];
    const int   i2 = g_idx[base + 2];
    const float w0 = g_w[base + 0];
    const float w1 = g_w[base + 1];
    const float w2 = g_w[base + 2];

    const float4* f = reinterpret_cast<const float4*>(feat);
    const float4 a = __ldg(f + (size_t)i0 * C4 + cg);
    const float4 b = __ldg(f + (size_t)i1 * C4 + cg);
    const float4 c = __ldg(f + (size_t)i2 * C4 + cg);

    float4 o;
    o.x = fmaf(w2, c.x, fmaf(w1, b.x, w0 * a.x));
    o.y = fmaf(w2, c.y, fmaf(w1, b.y, w0 * a.y));
    o.z = fmaf(w2, c.z, fmaf(w1, b.z, w0 * a.z));
    o.w = fmaf(w2, c.w, fmaf(w1, b.w, w0 * a.w));

    reinterpret_cast<float4*>(out)[t] = o;
}

extern "C" void kernel_launch(void* const* d_in, const int* in_sizes, int n_in,
                              void* d_out, int out_size)
{
    const float* xyz     = (const float*)d_in[0];
    const float* new_xyz = (const float*)d_in[1];
    const float* feat    = (const float*)d_in[2];

    const int B    = in_sizes[3];
    const int Ntot = in_sizes[0] / 3;
    const int Mtot = in_sizes[1] / 3;
    const int N    = Ntot / B;
    const int M    = Mtot / B;
    const int C    = in_sizes[2] / Ntot;

    const int cells = B * G3;
    zero_kernel<<<(cells + 255) / 256, 256>>>(cells);
    count_kernel<false><<<(Ntot + 255) / 256, 256>>>(xyz, N, Ntot);
    count_kernel<true ><<<(Mtot + 255) / 256, 256>>>(new_xyz, M, Mtot);
    scan_kernel<<<dim3(B, 2), 1024>>>();
    scatter_kernel<false><<<(Ntot + 255) / 256, 256>>>(xyz, N, Ntot);
    scatter_kernel<true ><<<(Mtot + 255) / 256, 256>>>(new_xyz, M, Mtot);

    dim3 g1((M + KNN_BLOCK - 1) / KNN_BLOCK, B);
    knn_grid<<<g1, KNN_BLOCK>>>(N, M);

    const int C4    = C / 4;
    const int total = Mtot * C4;
    interp_kernel<<<(total + 255) / 256, 256>>>(feat, (float*)d_out, C4, total);
}

// round 7
// speedup vs baseline: 3.1327x; 1.1431x over previous
#include <cuda_runtime.h>
#include <float.h>

// ---------------------------------------------------------------------------
// FeatPropagation via uniform-grid EXACT k=3 NN + inverse-distance interp.
//
// R7: block-per-query-cell kNN. R6's per-thread walk was latency-bound on
// scattered per-candidate LDGs (L2-hit chains, MLP~1). Now each block stages
// its cell's 3x3x3 candidate neighborhood into SMEM once (coalesced), and
// all queries of the cell scan SMEM with broadcast LDS.128 + group-min
// prefilter. Rare queries (~5%, outer region) that fail the r=1 stop bound
// fall back to the per-thread global ring walk from r=2.
//
// Ranking stays BIT-EXACT vs the JAX reference (GEMM-form d2 with explicit
// rounding intrinsics); (d2, index) lexicographic insert == top_k
// lowest-index tie-break, independent of scatter order. Stop bound is
// conservative (MARGIN >> reference rounding error) -> exact result.
// ---------------------------------------------------------------------------

#define G      16
#define G3     (G * G * G)
#define GLO    (-4.0f)
#define HV     0.5f
#define INVH   2.0f
#define MAXB   8
#define MARGIN 2e-4f

// point grid
__device__ int    g_cnt[MAXB * G3];
__device__ int    g_start[MAXB * (G3 + 1)];
__device__ int    g_cur[MAXB * G3];
__device__ float4 g_pts[1 << 15];      // sorted points {x,y,z,s2}
__device__ int    g_pid[1 << 15];      // sorted slot -> original global index
// query grid
__device__ int    g_qcnt[MAXB * G3];
__device__ int    g_qstart[MAXB * (G3 + 1)];
__device__ int    g_qcur[MAXB * G3];
__device__ float4 g_qpts[1 << 17];     // sorted queries {x,y,z,q2}
__device__ int    g_qid[1 << 17];      // sorted slot -> original global index

#define CAPQ (3 * (1 << 17))
__device__ int   g_idx[CAPQ];
__device__ float g_w[CAPQ];

__device__ __forceinline__ int cell1(float v) {
    int c = (int)floorf((v - GLO) * INVH);
    return min(max(c, 0), G - 1);
}

__global__ void zero_kernel(int cells) {
    int i = blockIdx.x * blockDim.x + threadIdx.x;
    if (i < cells) { g_cnt[i] = 0; g_qcnt[i] = 0; }
}

template <bool QRY>
__global__ void count_kernel(const float* __restrict__ src, int P, int total) {
    int i = blockIdx.x * blockDim.x + threadIdx.x;
    if (i >= total) return;
    int b = i / P;
    float x = src[3 * i], y = src[3 * i + 1], z = src[3 * i + 2];
    int c = (cell1(z) * G + cell1(y)) * G + cell1(x);
    atomicAdd((QRY ? g_qcnt : g_cnt) + b * G3 + c, 1);
}

// grid (B, 2): y==0 point counters, y==1 query counters. 4 cells/thread.
__global__ void __launch_bounds__(1024) scan_kernel() {
    const int b = blockIdx.x;
    int* cnt   = (blockIdx.y ? g_qcnt   : g_cnt)   + b * G3;
    int* start = (blockIdx.y ? g_qstart : g_start) + b * (G3 + 1);
    int* cur   = (blockIdx.y ? g_qcur   : g_cur)   + b * G3;

    const int tid = threadIdx.x;
    const int CH  = G3 / 1024;                            // 4
    __shared__ int sm[1024];

    const int lo = tid * CH;
    int c0 = cnt[lo], c1 = cnt[lo + 1], c2 = cnt[lo + 2], c3 = cnt[lo + 3];
    const int sum = c0 + c1 + c2 + c3;
    sm[tid] = sum;
    __syncthreads();
    for (int off = 1; off < 1024; off <<= 1) {            // Hillis-Steele
        int v = (tid >= off) ? sm[tid - off] : 0;
        __syncthreads();
        sm[tid] += v;
        __syncthreads();
    }
    int run = sm[tid] - sum;
    start[lo]     = run;  cur[lo]     = run;  run += c0;
    start[lo + 1] = run;  cur[lo + 1] = run;  run += c1;
    start[lo + 2] = run;  cur[lo + 2] = run;  run += c2;
    start[lo + 3] = run;  cur[lo + 3] = run;
    if (tid == 1023) start[G3] = sm[1023];
}

template <bool QRY>
__global__ void scatter_kernel(const float* __restrict__ src, int P, int total) {
    int i = blockIdx.x * blockDim.x + threadIdx.x;
    if (i >= total) return;
    int b = i / P;
    float x = src[3 * i], y = src[3 * i + 1], z = src[3 * i + 2];
    int c = (cell1(z) * G + cell1(y)) * G + cell1(x);
    int pos = atomicAdd((QRY ? g_qcur : g_cur) + b * G3 + c, 1);
    float s2 = __fadd_rn(__fadd_rn(__fmul_rn(x, x), __fmul_rn(y, y)),
                         __fmul_rn(z, z));
    if (QRY) { g_qpts[b * P + pos] = make_float4(x, y, z, s2);
               g_qid [b * P + pos] = i; }
    else     { g_pts [b * P + pos] = make_float4(x, y, z, s2);
               g_pid [b * P + pos] = i; }
}

// ---------------------------------------------------------------------------
// knn_cell: one block per (cell, batch). Stage 3x3x3 candidates in SMEM.
// ---------------------------------------------------------------------------
#define KNN_T  128
#define CAP_C  1280          // SMEM candidate chunk (float4 20KB + int 5KB)

__global__ void __launch_bounds__(KNN_T)
knn_cell(int N, int M)
{
    const int b = blockIdx.y;
    const int c = blockIdx.x;
    const int bsq = b * (G3 + 1);
    const int qs  = g_qstart[bsq + c];
    const int qe  = g_qstart[bsq + c + 1];
    if (qs == qe) return;                 // uniform early exit

    const int cz = c / (G * G);
    const int cy = (c / G) % G;
    const int cx = c % G;

    const int bs    = b * (G3 + 1);
    const int pbase = b * N;
    const int qbase = b * M;
    const int tid   = threadIdx.x;

    __shared__ int    rowS[9], rowE[9];
    __shared__ float4 spts[CAP_C];
    __shared__ int    sid[CAP_C];

    if (tid < 9) {
        const int dz = tid / 3 - 1, dy = tid % 3 - 1;
        const int z = cz + dz, y = cy + dy;
        int s = 0, e = 0;
        if (z >= 0 && z < G && y >= 0 && y < G) {
            const int xlo = max(cx - 1, 0), xhi = min(cx + 1, G - 1);
            const int row = (z * G + y) * G;
            s = g_start[bs + row + xlo];
            e = g_start[bs + row + xhi + 1];
        }
        rowS[tid] = s; rowE[tid] = e;
    }
    __syncthreads();

    for (int q0 = qs; q0 < qe; q0 += KNN_T) {
        const int  myq = qbase + q0 + tid;
        const bool act = (q0 + tid) < qe;

        float qx = 0.f, qy = 0.f, qz = 0.f, q2 = 0.f;
        int qid = 0;
        if (act) {
            const float4 Q = g_qpts[myq];
            qx = Q.x; qy = Q.y; qz = Q.z; q2 = Q.w;
            qid = g_qid[myq];
        }

        float d0 = 1e30f, d1 = 1e30f, d2v = 1e30f;
        int   i0 = -1,    i1 = -1,    i2 = -1;

        auto ins = [&](float dd, int id) {
            if (dd < d2v || (dd == d2v && id < i2)) {
                if (dd < d1 || (dd == d1 && id < i1)) {
                    d2v = d1; i2 = i1;
                    if (dd < d0 || (dd == d0 && id < i0)) {
                        d1 = d0; i1 = i0; d0 = dd; i0 = id;
                    } else { d1 = dd; i1 = id; }
                } else { d2v = dd; i2 = id; }
            }
        };
        auto dist2 = [&](const float4& P) -> float {
            const float cross = __fmaf_rn(qz, P.z,
                                  __fmaf_rn(qy, P.y, __fmul_rn(qx, P.x)));
            return __fmaf_rn(-2.0f, cross, __fadd_rn(q2, P.w));
        };

        // ---- chunked SMEM scan of the 3x3x3 box (block-uniform control) ----
        int row = 0, pos = rowS[0], gstart = 0;   // gstart: base sorted slot of chunk? (ids come from sid)
        while (row < 9) {
            int filled = 0;
            while (row < 9 && filled < CAP_C) {
                const int avail = rowE[row] - pos;
                const int take  = min(avail, CAP_C - filled);
                for (int i = tid; i < take; i += KNN_T) {
                    spts[filled + i] = g_pts[pbase + pos + i];
                    sid [filled + i] = g_pid[pbase + pos + i];
                }
                filled += take; pos += take;
                if (pos >= rowE[row]) { row++; if (row < 9) pos = rowS[row]; }
            }
            __syncthreads();

            if (act) {
                const int k4 = filled & ~3;
                for (int j = 0; j < k4; j += 4) {
                    const float dd0 = dist2(spts[j + 0]);
                    const float dd1 = dist2(spts[j + 1]);
                    const float dd2 = dist2(spts[j + 2]);
                    const float dd3 = dist2(spts[j + 3]);
                    const float gm  = fminf(fminf(dd0, dd1), fminf(dd2, dd3));
                    if (gm <= d2v) {          // '<=' keeps tie-break exact
                        ins(dd0, sid[j + 0]);
                        ins(dd1, sid[j + 1]);
                        ins(dd2, sid[j + 2]);
                        ins(dd3, sid[j + 3]);
                    }
                }
                for (int j = k4; j < filled; j++)
                    ins(dist2(spts[j]), sid[j]);
            }
            __syncthreads();
        }
        (void)gstart;

        if (act) {
            // ---- stop check for r=1 box; rare fallback: ring walk r>=2 ----
            bool done = false;
            {
                const float fxl = (cx - 1 <= 0)     ? 1e30f : qx - (GLO + (cx - 1) * HV);
                const float fxh = (cx + 1 >= G - 1) ? 1e30f : (GLO + (cx + 2) * HV) - qx;
                const float fyl = (cy - 1 <= 0)     ? 1e30f : qy - (GLO + (cy - 1) * HV);
                const float fyh = (cy + 1 >= G - 1) ? 1e30f : (GLO + (cy + 2) * HV) - qy;
                const float fzl = (cz - 1 <= 0)     ? 1e30f : qz - (GLO + (cz - 1) * HV);
                const float fzh = (cz + 1 >= G - 1) ? 1e30f : (GLO + (cz + 2) * HV) - qz;
                const float lb  = fminf(fminf(fminf(fxl, fxh), fminf(fyl, fyh)),
                                        fminf(fzl, fzh));
                if (lb >= 1e29f) done = true;
                else if (i2 >= 0 && lb > 0.0f && d2v + MARGIN <= lb * lb) done = true;
            }

            if (!done) {
                auto process = [&](int c0, int c1) {
                    const int s = __ldg(&g_start[bs + c0]);
                    const int e = __ldg(&g_start[bs + c1 + 1]);
                    for (int p = s; p < e; p++) {
                        const float4 P  = g_pts[pbase + p];
                        ins(dist2(P), g_pid[pbase + p]);
                    }
                };
                for (int r = 2; ; r++) {
                    const int zlo = max(cz - r, 0), zhi = min(cz + r, G - 1);
                    const int ylo = max(cy - r, 0), yhi = min(cy + r, G - 1);
                    const int xlo = max(cx - r, 0), xhi = min(cx + r, G - 1);
                    for (int z = zlo; z <= zhi; z++) {
                        const bool ez = (z == cz - r) || (z == cz + r);
                        for (int y = ylo; y <= yhi; y++) {
                            const bool ey = ez || (y == cy - r) || (y == cy + r);
                            const int rw = (z * G + y) * G;
                            if (ey) {
                                process(rw + xlo, rw + xhi);
                            } else {
                                if (cx - r >= 0)     process(rw + cx - r, rw + cx - r);
                                if (cx + r <= G - 1) process(rw + cx + r, rw + cx + r);
                            }
                        }
                    }
                    const float fxl = (cx - r <= 0)     ? 1e30f : qx - (GLO + (cx - r) * HV);
                    const float fxh = (cx + r >= G - 1) ? 1e30f : (GLO + (cx + r + 1) * HV) - qx;
                    const float fyl = (cy - r <= 0)     ? 1e30f : qy - (GLO + (cy - r) * HV);
                    const float fyh = (cy + r >= G - 1) ? 1e30f : (GLO + (cy + r + 1) * HV) - qy;
                    const float fzl = (cz - r <= 0)     ? 1e30f : qz - (GLO + (cz - r) * HV);
                    const float fzh = (cz + r >= G - 1) ? 1e30f : (GLO + (cz + r + 1) * HV) - qz;
                    const float lb  = fminf(fminf(fminf(fxl, fxh), fminf(fyl, fyh)),
                                            fminf(fzl, fzh));
                    if (lb >= 1e29f) break;
                    if (i2 >= 0 && lb > 0.0f && d2v + MARGIN <= lb * lb) break;
                }
            }

            const float e0 = sqrtf(fmaxf(d0,  1e-12f));
            const float e1 = sqrtf(fmaxf(d1,  1e-12f));
            const float e2 = sqrtf(fmaxf(d2v, 1e-12f));
            const float r0 = __fdiv_rn(1.0f, __fadd_rn(e0, 1e-8f));
            const float r1 = __fdiv_rn(1.0f, __fadd_rn(e1, 1e-8f));
            const float r2 = __fdiv_rn(1.0f, __fadd_rn(e2, 1e-8f));
            const float s  = __fadd_rn(__fadd_rn(r0, r1), r2);

            const int base  = 3 * qid;
            g_idx[base + 0] = i0;
            g_idx[base + 1] = i1;
            g_idx[base + 2] = i2;
            g_w[base + 0]   = __fdiv_rn(r0, s);
            g_w[base + 1]   = __fdiv_rn(r1, s);
            g_w[base + 2]   = __fdiv_rn(r2, s);
        }
        __syncthreads();
    }
}

__global__ void __launch_bounds__(256)
interp_kernel(const float* __restrict__ feat, float* __restrict__ out,
              int C4, int total)
{
    const int t = blockIdx.x * 256 + threadIdx.x;
    if (t >= total) return;

    const int q  = t / C4;
    const int cg = t - q * C4;

    const int   base = 3 * q;
    const int   i0 = g_idx[base + 0];
    const int   i1 = g_idx[base + 1];
    const int   i2 = g_idx[base + 2];
    const float w0 = g_w[base + 0];
    const float w1 = g_w[base + 1];
    const float w2 = g_w[base + 2];

    const float4* f = reinterpret_cast<const float4*>(feat);
    const float4 a = __ldg(f + (size_t)i0 * C4 + cg);
    const float4 b = __ldg(f + (size_t)i1 * C4 + cg);
    const float4 c = __ldg(f + (size_t)i2 * C4 + cg);

    float4 o;
    o.x = fmaf(w2, c.x, fmaf(w1, b.x, w0 * a.x));
    o.y = fmaf(w2, c.y, fmaf(w1, b.y, w0 * a.y));
    o.z = fmaf(w2, c.z, fmaf(w1, b.z, w0 * a.z));
    o.w = fmaf(w2, c.w, fmaf(w1, b.w, w0 * a.w));

    reinterpret_cast<float4*>(out)[t] = o;
}

extern "C" void kernel_launch(void* const* d_in, const int* in_sizes, int n_in,
                              void* d_out, int out_size)
{
    const float* xyz     = (const float*)d_in[0];
    const float* new_xyz = (const float*)d_in[1];
    const float* feat    = (const float*)d_in[2];

    const int B    = in_sizes[3];
    const int Ntot = in_sizes[0] / 3;
    const int Mtot = in_sizes[1] / 3;
    const int N    = Ntot / B;
    const int M    = Mtot / B;
    const int C    = in_sizes[2] / Ntot;

    const int cells = B * G3;
    zero_kernel<<<(cells + 255) / 256, 256>>>(cells);
    count_kernel<false><<<(Ntot + 255) / 256, 256>>>(xyz, N, Ntot);
    count_kernel<true ><<<(Mtot + 255) / 256, 256>>>(new_xyz, M, Mtot);
    scan_kernel<<<dim3(B, 2), 1024>>>();
    scatter_kernel<false><<<(Ntot + 255) / 256, 256>>>(xyz, N, Ntot);
    scatter_kernel<true ><<<(Mtot + 255) / 256, 256>>>(new_xyz, M, Mtot);

    knn_cell<<<dim3(G3, B), KNN_T>>>(N, M);

    const int C4    = C / 4;
    const int total = Mtot * C4;
    interp_kernel<<<(total + 255) / 256, 256>>>(feat, (float*)d_out, C4, total);
}